// round 1
// baseline (speedup 1.0000x reference)
#include <cuda_runtime.h>
#include <math.h>

#define NNODE 20000
#define NEDGE 320000
#define EMB   64
#define RAD   32
#define NC    (NNODE * EMB)          // 1,280,000
#define GSTRIDE 33                   // 32 rbf sums + 1 env sum

// ---------------- scratch (device globals; no runtime allocation) ----------
__device__ float g_comp[9][NC];      // decomposed components (comp-major)
__device__ float g_mix [9][NC];      // channel-mixed components
__device__ float g_G[NNODE * GSTRIDE]; // scattered rbf sums per node
__device__ float g_C[NNODE * 3 * EMB]; // per-node coefficients (I,A,S blocks)

// ---------------- K1: normalize + decompose X -----------------------------
__global__ void k_decompose(const float* __restrict__ X) {
    int idx = blockIdx.x * blockDim.x + threadIdx.x;   // n*EMB + c
    if (idx >= NC) return;
    const float* x = X + (size_t)idx * 9;
    float v[9];
#pragma unroll
    for (int k = 0; k < 9; k++) v[k] = x[k];
    float fr = 0.f;
#pragma unroll
    for (int k = 0; k < 9; k++) fr += v[k] * v[k];
    float inv = 1.0f / (fr + 1.0f);
#pragma unroll
    for (int k = 0; k < 9; k++) v[k] *= inv;
    float dm = (v[0] + v[4] + v[8]) * (1.0f / 3.0f);
    g_comp[0][idx] = dm;                       // iso
    g_comp[1][idx] = 0.5f * (v[1] - v[3]);     // a01
    g_comp[2][idx] = 0.5f * (v[2] - v[6]);     // a02
    g_comp[3][idx] = 0.5f * (v[5] - v[7]);     // a12
    g_comp[4][idx] = v[0] - dm;                // s00
    g_comp[5][idx] = v[4] - dm;                // s11
    g_comp[6][idx] = 0.5f * (v[1] + v[3]);     // s01
    g_comp[7][idx] = 0.5f * (v[2] + v[6]);     // s02
    g_comp[8][idx] = 0.5f * (v[5] + v[7]);     // s12
}

// ---------------- K zero ---------------------------------------------------
__global__ void k_zero_G() {
    int i = blockIdx.x * blockDim.x + threadIdx.x;
    if (i < NNODE * GSTRIDE) g_G[i] = 0.f;
}

// ---------------- K2: edge scatter of rbf features -------------------------
__global__ void k_edge(const float* __restrict__ dist, const int* __restrict__ nbr) {
    int e = blockIdx.x * blockDim.x + threadIdx.x;
    if (e >= NEDGE) return;
    float d = dist[e];
    int t = nbr[e];
    const float MU0  = 0.006737946999085467f;           // exp(-5)
    const float DMU  = (1.0f - 0.006737946999085467f) / 31.0f;
    const float AA   = 0.0625f * (1.0f - 0.006737946999085467f);
    const float BETA = 1.0f / (AA * AA);                // ~259.485
    float ed  = expf(-d);
    float env = (d < 5.0f) ? 0.5f * (cosf(3.14159265358979323846f * d * 0.2f) + 1.0f) : 0.f;
    float* Gp = g_G + (size_t)t * GSTRIDE;
#pragma unroll
    for (int k = 0; k < RAD; k++) {
        float df  = ed - (MU0 + (float)k * DMU);
        float phi = expf(-BETA * df * df);
        atomicAdd(Gp + k, env * phi);
    }
    atomicAdd(Gp + RAD, env);
}

// ---------------- K3/K6: channel mixing (9 GEMMs, tiled) -------------------
// out[comp][n*64+o] = sum_c in[comp][n*64+c] * W[o*64+c]
__global__ void k_tlin(const float* __restrict__ WI,
                       const float* __restrict__ WA,
                       const float* __restrict__ WS) {
    __shared__ float sIn[64][65];   // [k][node]
    __shared__ float sW [64][65];   // [k][o]
    int compi = blockIdx.y;
    const float* W = (compi == 0) ? WI : (compi < 4 ? WA : WS);
    const float* in = &g_comp[compi][0];
    float* out = &g_mix[compi][0];
    int tid = threadIdx.x;              // 256
    int node0 = blockIdx.x * 64;
    for (int i = tid; i < 4096; i += 256) {
        int o = i >> 6, c = i & 63;
        sW[c][o] = W[i];
    }
    for (int i = tid; i < 4096; i += 256) {
        int nn = i >> 6, c = i & 63;
        int n = node0 + nn;
        sIn[c][nn] = (n < NNODE) ? in[n * 64 + c] : 0.f;
    }
    __syncthreads();
    int tx = tid & 15, ty = tid >> 4;
    float acc[4][4] = {};
#pragma unroll 16
    for (int kk = 0; kk < 64; kk++) {
        float a[4], b[4];
#pragma unroll
        for (int i = 0; i < 4; i++) a[i] = sIn[kk][ty * 4 + i];
#pragma unroll
        for (int j = 0; j < 4; j++) b[j] = sW[kk][tx * 4 + j];
#pragma unroll
        for (int i = 0; i < 4; i++)
#pragma unroll
            for (int j = 0; j < 4; j++)
                acc[i][j] += a[i] * b[j];
    }
#pragma unroll
    for (int i = 0; i < 4; i++) {
        int n = node0 + ty * 4 + i;
        if (n < NNODE) {
#pragma unroll
            for (int j = 0; j < 4; j++)
                out[n * 64 + tx * 4 + j] = acc[i][j];
        }
    }
}

// ---------------- K4: per-node coefficient GEMM ----------------------------
// C[n][o] = Wd[o,:] . G[n,0:32] + b[o] * G[n,32]
#define NODES_PER_BLK 16
__global__ void k_coeff(const float* __restrict__ Wd, const float* __restrict__ bd) {
    __shared__ float sWd[192][33];
    __shared__ float sG[NODES_PER_BLK][33];
    int tid = threadIdx.x;              // 192
    for (int i = tid; i < 192 * 32; i += 192) {
        int o = i >> 5, k = i & 31;
        sWd[o][k] = Wd[i];
    }
    float bo = bd[tid];
    int n0 = blockIdx.x * NODES_PER_BLK;
    for (int i = tid; i < NODES_PER_BLK * GSTRIDE; i += 192) {
        int nn = i / GSTRIDE, k = i % GSTRIDE;
        int n = n0 + nn;
        sG[nn][k] = (n < NNODE) ? g_G[n * GSTRIDE + k] : 0.f;
    }
    __syncthreads();
    for (int nn = 0; nn < NODES_PER_BLK; nn++) {
        int n = n0 + nn;
        if (n >= NNODE) break;
        float acc = bo * sG[nn][32];
#pragma unroll
        for (int k = 0; k < 32; k++) acc += sWd[tid][k] * sG[nn][k];
        g_C[n * 192 + tid] = acc;
    }
}

// helper: build full 3x3 from 9 components
__device__ __forceinline__ void build33(const float c[9], float Y[3][3]) {
    // c: iso, a01,a02,a12, s00,s11,s01,s02,s12
    Y[0][0] = c[0] + c[4];
    Y[0][1] = c[1] + c[6];
    Y[0][2] = c[2] + c[7];
    Y[1][0] = -c[1] + c[6];
    Y[1][1] = c[0] + c[5];
    Y[1][2] = c[3] + c[8];
    Y[2][0] = -c[2] + c[7];
    Y[2][1] = -c[3] + c[8];
    Y[2][2] = c[0] - c[4] - c[5];
}

// ---------------- K5: anticommutator + renorm + decompose ------------------
__global__ void k_mix2() {
    int idx = blockIdx.x * blockDim.x + threadIdx.x;
    if (idx >= NC) return;
    int n = idx >> 6, c = idx & 63;
    float cI = g_C[n * 192 + c];
    float cA = g_C[n * 192 + 64 + c];
    float cS = g_C[n * 192 + 128 + c];
    float xc[9], yc[9];
#pragma unroll
    for (int k = 0; k < 9; k++) xc[k] = g_comp[k][idx];
#pragma unroll
    for (int k = 0; k < 9; k++) yc[k] = g_mix[k][idx];
    // M components = per-part scaled X components
    float mc[9];
    mc[0] = cI * xc[0];
    mc[1] = cA * xc[1]; mc[2] = cA * xc[2]; mc[3] = cA * xc[3];
    mc[4] = cS * xc[4]; mc[5] = cS * xc[5]; mc[6] = cS * xc[6];
    mc[7] = cS * xc[7]; mc[8] = cS * xc[8];
    float Y[3][3], M[3][3], Z[3][3];
    build33(yc, Y);
    build33(mc, M);
#pragma unroll
    for (int i = 0; i < 3; i++)
#pragma unroll
        for (int j = 0; j < 3; j++) {
            float s = 0.f;
#pragma unroll
            for (int k = 0; k < 3; k++)
                s += Y[i][k] * M[k][j] + M[i][k] * Y[k][j];
            Z[i][j] = s;
        }
    float norm = 0.f;
#pragma unroll
    for (int i = 0; i < 3; i++)
#pragma unroll
        for (int j = 0; j < 3; j++) {
            float t = Z[i][j] + 1.0f;
            norm += t * t;
        }
    float inv = 1.0f / norm;
    float dm = (Z[0][0] + Z[1][1] + Z[2][2]) * (1.0f / 3.0f);
    g_comp[0][idx] = dm * inv;
    g_comp[1][idx] = 0.5f * (Z[0][1] - Z[1][0]) * inv;
    g_comp[2][idx] = 0.5f * (Z[0][2] - Z[2][0]) * inv;
    g_comp[3][idx] = 0.5f * (Z[1][2] - Z[2][1]) * inv;
    g_comp[4][idx] = (Z[0][0] - dm) * inv;
    g_comp[5][idx] = (Z[1][1] - dm) * inv;
    g_comp[6][idx] = 0.5f * (Z[0][1] + Z[1][0]) * inv;
    g_comp[7][idx] = 0.5f * (Z[0][2] + Z[2][0]) * inv;
    g_comp[8][idx] = 0.5f * (Z[1][2] + Z[2][1]) * inv;
}

// ---------------- K7: final Y + Y@Y ----------------------------------------
__global__ void k_final(float* __restrict__ out) {
    int idx = blockIdx.x * blockDim.x + threadIdx.x;
    if (idx >= NC) return;
    float yc[9];
#pragma unroll
    for (int k = 0; k < 9; k++) yc[k] = g_mix[k][idx];
    float Y[3][3];
    build33(yc, Y);
    float* o = out + (size_t)idx * 9;
#pragma unroll
    for (int i = 0; i < 3; i++)
#pragma unroll
        for (int j = 0; j < 3; j++) {
            float s = Y[i][j];
#pragma unroll
            for (int k = 0; k < 3; k++)
                s += Y[i][k] * Y[k][j];
            o[i * 3 + j] = s;
        }
}

// ---------------- launch ----------------------------------------------------
extern "C" void kernel_launch(void* const* d_in, const int* in_sizes, int n_in,
                              void* d_out, int out_size) {
    const float* X      = (const float*)d_in[0];
    const float* dist   = (const float*)d_in[1];
    const int*   nbr    = (const int*)  d_in[2];
    const float* WI_pre = (const float*)d_in[3];
    const float* WA_pre = (const float*)d_in[4];
    const float* WS_pre = (const float*)d_in[5];
    const float* WI_post= (const float*)d_in[6];
    const float* WA_post= (const float*)d_in[7];
    const float* WS_post= (const float*)d_in[8];
    const float* Wd     = (const float*)d_in[9];
    const float* bd     = (const float*)d_in[10];
    float* out = (float*)d_out;

    k_decompose<<<(NC + 255) / 256, 256>>>(X);
    k_zero_G<<<(NNODE * GSTRIDE + 255) / 256, 256>>>();
    k_edge<<<(NEDGE + 127) / 128, 128>>>(dist, nbr);
    dim3 gt((NNODE + 63) / 64, 9);
    k_tlin<<<gt, 256>>>(WI_pre, WA_pre, WS_pre);
    k_coeff<<<(NNODE + NODES_PER_BLK - 1) / NODES_PER_BLK, 192>>>(Wd, bd);
    k_mix2<<<(NC + 255) / 256, 256>>>();
    k_tlin<<<gt, 256>>>(WI_post, WA_post, WS_post);
    k_final<<<(NC + 255) / 256, 256>>>(out);
}

// round 2
// speedup vs baseline: 1.0617x; 1.0617x over previous
#include <cuda_runtime.h>
#include <math.h>

#define NNODE 20000
#define NEDGE 320000
#define EMB   64
#define RAD   32
#define NC    (NNODE * EMB)          // 1,280,000
#define GSTRIDE 33                   // 32 rbf sums + 1 env sum

// ---------------- scratch (device globals; no runtime allocation) ----------
__device__ float g_comp[9][NC];        // decomposed components (comp-major)
__device__ float g_mix [9][NC];        // channel-mixed components
__device__ float g_G[NNODE * GSTRIDE]; // scattered rbf sums per node
__device__ float g_C[NNODE * 3 * EMB]; // per-node coefficients (I,A,S blocks)
__device__ float g_Wt[6][EMB * EMB];   // transposed weights Wt[c*64+o] = W[o*64+c]

// ---------------- f32x2 helpers --------------------------------------------
__device__ __forceinline__ unsigned long long pack2(float x) {
    unsigned long long r;
    asm("mov.b64 %0, {%1, %1};" : "=l"(r) : "f"(x));
    return r;
}
__device__ __forceinline__ void ffma2(unsigned long long& d,
                                      unsigned long long a,
                                      unsigned long long b) {
    asm("fma.rn.f32x2 %0, %1, %2, %0;" : "+l"(d) : "l"(a), "l"(b));
}

// ---------------- K0: transpose the 6 weight matrices -----------------------
__global__ void k_transW(const float* __restrict__ W0, const float* __restrict__ W1,
                         const float* __restrict__ W2, const float* __restrict__ W3,
                         const float* __restrict__ W4, const float* __restrict__ W5) {
    int i = blockIdx.x * blockDim.x + threadIdx.x;   // 6*4096
    if (i >= 6 * EMB * EMB) return;
    int m = i >> 12, r = i & 4095;
    int o = r >> 6, c = r & 63;
    const float* W = (m == 0) ? W0 : (m == 1) ? W1 : (m == 2) ? W2 :
                     (m == 3) ? W3 : (m == 4) ? W4 : W5;
    g_Wt[m][c * EMB + o] = W[o * EMB + c];
}

// ---------------- K1: normalize + decompose X (+ zero g_G) ------------------
__global__ void k_decompose(const float* __restrict__ X) {
    int idx = blockIdx.x * blockDim.x + threadIdx.x;   // n*EMB + c
    if (idx < NNODE * GSTRIDE) g_G[idx] = 0.f;
    if (idx >= NC) return;
    const float* x = X + (size_t)idx * 9;
    float v[9];
#pragma unroll
    for (int k = 0; k < 9; k++) v[k] = x[k];
    float fr = 0.f;
#pragma unroll
    for (int k = 0; k < 9; k++) fr += v[k] * v[k];
    float inv = 1.0f / (fr + 1.0f);
#pragma unroll
    for (int k = 0; k < 9; k++) v[k] *= inv;
    float dm = (v[0] + v[4] + v[8]) * (1.0f / 3.0f);
    g_comp[0][idx] = dm;
    g_comp[1][idx] = 0.5f * (v[1] - v[3]);
    g_comp[2][idx] = 0.5f * (v[2] - v[6]);
    g_comp[3][idx] = 0.5f * (v[5] - v[7]);
    g_comp[4][idx] = v[0] - dm;
    g_comp[5][idx] = v[4] - dm;
    g_comp[6][idx] = 0.5f * (v[1] + v[3]);
    g_comp[7][idx] = 0.5f * (v[2] + v[6]);
    g_comp[8][idx] = 0.5f * (v[5] + v[7]);
}

// ---------------- K2: edge scatter of rbf features ---------------------------
__global__ void k_edge(const float* __restrict__ dist, const int* __restrict__ nbr) {
    int e = blockIdx.x * blockDim.x + threadIdx.x;
    if (e >= NEDGE) return;
    float d = dist[e];
    int t = nbr[e];
    const float MU0  = 0.006737946999085467f;           // exp(-5)
    const float DMU  = (1.0f - 0.006737946999085467f) / 31.0f;
    const float AA   = 0.0625f * (1.0f - 0.006737946999085467f);
    const float BETA = 1.0f / (AA * AA);
    float ed  = __expf(-d);
    float env = (d < 5.0f) ? 0.5f * (__cosf(3.14159265358979323846f * d * 0.2f) + 1.0f) : 0.f;
    float* Gp = g_G + (size_t)t * GSTRIDE;
#pragma unroll
    for (int k = 0; k < RAD; k++) {
        float df  = ed - (MU0 + (float)k * DMU);
        float phi = __expf(-BETA * df * df);
        atomicAdd(Gp + k, env * phi);
    }
    atomicAdd(Gp + RAD, env);
}

// ---------------- K3/K6: channel mixing with f32x2 --------------------------
// out[comp][n*64+o] = sum_c in[comp][n*64+c] * W[o*64+c]
// block: 128 nodes x 64 outs, one comp. thread: 4 nodes x 8 outs.
__global__ void __launch_bounds__(256) k_tlin(int wbase) {
    __shared__ float sIn[128][68];   // [node][c]   (conflict-free fill + bcast reads)
    __shared__ float sW [64][68];    // [c][o]      (from pre-transposed g_Wt)
    int compi = blockIdx.y;
    int wsel  = wbase + ((compi == 0) ? 0 : (compi < 4 ? 1 : 2));
    const float* __restrict__ Wt = g_Wt[wsel];
    const float* __restrict__ in = &g_comp[compi][0];
    float* __restrict__ out = &g_mix[compi][0];
    int tid = threadIdx.x;
    int node0 = blockIdx.x * 128;

    // fill sW: 1024 float4
    for (int i = tid; i < 1024; i += 256) {
        int c = i >> 4, o4 = (i & 15) << 2;
        *(float4*)&sW[c][o4] = *(const float4*)&Wt[c * EMB + o4];
    }
    // fill sIn: 2048 float4
    for (int i = tid; i < 2048; i += 256) {
        int nn = i >> 4, c4 = (i & 15) << 2;
        int n = node0 + nn;
        float4 v = make_float4(0.f, 0.f, 0.f, 0.f);
        if (n < NNODE) v = *(const float4*)&in[n * EMB + c4];
        *(float4*)&sIn[nn][c4] = v;
    }
    __syncthreads();

    int tx = tid & 7;        // out group: o0 = tx*8
    int ty = tid >> 3;       // node group: n0 = ty*4
    unsigned long long acc[4][4] = {};
#pragma unroll 8
    for (int kk = 0; kk < 64; kk++) {
        unsigned long long pa[4];
#pragma unroll
        for (int i = 0; i < 4; i++) pa[i] = pack2(sIn[ty * 4 + i][kk]);
        float4 b01 = *(float4*)&sW[kk][tx * 8];
        float4 b23 = *(float4*)&sW[kk][tx * 8 + 4];
        unsigned long long pb[4];
        pb[0] = *(unsigned long long*)&b01.x;
        pb[1] = *(unsigned long long*)&b01.z;
        pb[2] = *(unsigned long long*)&b23.x;
        pb[3] = *(unsigned long long*)&b23.z;
#pragma unroll
        for (int i = 0; i < 4; i++)
#pragma unroll
            for (int j = 0; j < 4; j++)
                ffma2(acc[i][j], pa[i], pb[j]);
    }
#pragma unroll
    for (int i = 0; i < 4; i++) {
        int n = node0 + ty * 4 + i;
        if (n < NNODE) {
            float* op = out + (size_t)n * EMB + tx * 8;
#pragma unroll
            for (int j = 0; j < 4; j++)
                *(unsigned long long*)(op + 2 * j) = acc[i][j];
        }
    }
}

// ---------------- K4: per-node coefficient GEMM ------------------------------
#define NODES_PER_BLK 16
__global__ void k_coeff(const float* __restrict__ Wd, const float* __restrict__ bd) {
    __shared__ float sWd[192][33];
    __shared__ float sG[NODES_PER_BLK][33];
    int tid = threadIdx.x;              // 192
    for (int i = tid; i < 192 * 32; i += 192) {
        int o = i >> 5, k = i & 31;
        sWd[o][k] = Wd[i];
    }
    float bo = bd[tid];
    int n0 = blockIdx.x * NODES_PER_BLK;
    for (int i = tid; i < NODES_PER_BLK * GSTRIDE; i += 192) {
        int nn = i / GSTRIDE, k = i % GSTRIDE;
        int n = n0 + nn;
        sG[nn][k] = (n < NNODE) ? g_G[n * GSTRIDE + k] : 0.f;
    }
    __syncthreads();
    for (int nn = 0; nn < NODES_PER_BLK; nn++) {
        int n = n0 + nn;
        if (n >= NNODE) break;
        float acc = bo * sG[nn][32];
#pragma unroll
        for (int k = 0; k < 32; k++) acc += sWd[tid][k] * sG[nn][k];
        g_C[n * 192 + tid] = acc;
    }
}

// helper: build full 3x3 from 9 components
__device__ __forceinline__ void build33(const float c[9], float Y[3][3]) {
    Y[0][0] = c[0] + c[4];
    Y[0][1] = c[1] + c[6];
    Y[0][2] = c[2] + c[7];
    Y[1][0] = -c[1] + c[6];
    Y[1][1] = c[0] + c[5];
    Y[1][2] = c[3] + c[8];
    Y[2][0] = -c[2] + c[7];
    Y[2][1] = -c[3] + c[8];
    Y[2][2] = c[0] - c[4] - c[5];
}

// ---------------- K5: anticommutator + renorm + decompose --------------------
__global__ void k_mix2() {
    int idx = blockIdx.x * blockDim.x + threadIdx.x;
    if (idx >= NC) return;
    int n = idx >> 6, c = idx & 63;
    float cI = g_C[n * 192 + c];
    float cA = g_C[n * 192 + 64 + c];
    float cS = g_C[n * 192 + 128 + c];
    float xc[9], yc[9];
#pragma unroll
    for (int k = 0; k < 9; k++) xc[k] = g_comp[k][idx];
#pragma unroll
    for (int k = 0; k < 9; k++) yc[k] = g_mix[k][idx];
    float mc[9];
    mc[0] = cI * xc[0];
    mc[1] = cA * xc[1]; mc[2] = cA * xc[2]; mc[3] = cA * xc[3];
    mc[4] = cS * xc[4]; mc[5] = cS * xc[5]; mc[6] = cS * xc[6];
    mc[7] = cS * xc[7]; mc[8] = cS * xc[8];
    float Y[3][3], M[3][3], Z[3][3];
    build33(yc, Y);
    build33(mc, M);
#pragma unroll
    for (int i = 0; i < 3; i++)
#pragma unroll
        for (int j = 0; j < 3; j++) {
            float s = 0.f;
#pragma unroll
            for (int k = 0; k < 3; k++)
                s += Y[i][k] * M[k][j] + M[i][k] * Y[k][j];
            Z[i][j] = s;
        }
    float norm = 0.f;
#pragma unroll
    for (int i = 0; i < 3; i++)
#pragma unroll
        for (int j = 0; j < 3; j++) {
            float t = Z[i][j] + 1.0f;
            norm += t * t;
        }
    float inv = 1.0f / norm;
    float dm = (Z[0][0] + Z[1][1] + Z[2][2]) * (1.0f / 3.0f);
    g_comp[0][idx] = dm * inv;
    g_comp[1][idx] = 0.5f * (Z[0][1] - Z[1][0]) * inv;
    g_comp[2][idx] = 0.5f * (Z[0][2] - Z[2][0]) * inv;
    g_comp[3][idx] = 0.5f * (Z[1][2] - Z[2][1]) * inv;
    g_comp[4][idx] = (Z[0][0] - dm) * inv;
    g_comp[5][idx] = (Z[1][1] - dm) * inv;
    g_comp[6][idx] = 0.5f * (Z[0][1] + Z[1][0]) * inv;
    g_comp[7][idx] = 0.5f * (Z[0][2] + Z[2][0]) * inv;
    g_comp[8][idx] = 0.5f * (Z[1][2] + Z[2][1]) * inv;
}

// ---------------- K7: final Y + Y@Y ------------------------------------------
__global__ void k_final(float* __restrict__ out) {
    int idx = blockIdx.x * blockDim.x + threadIdx.x;
    if (idx >= NC) return;
    float yc[9];
#pragma unroll
    for (int k = 0; k < 9; k++) yc[k] = g_mix[k][idx];
    float Y[3][3];
    build33(yc, Y);
    float* o = out + (size_t)idx * 9;
#pragma unroll
    for (int i = 0; i < 3; i++)
#pragma unroll
        for (int j = 0; j < 3; j++) {
            float s = Y[i][j];
#pragma unroll
            for (int k = 0; k < 3; k++)
                s += Y[i][k] * Y[k][j];
            o[i * 3 + j] = s;
        }
}

// ---------------- launch ------------------------------------------------------
extern "C" void kernel_launch(void* const* d_in, const int* in_sizes, int n_in,
                              void* d_out, int out_size) {
    const float* X      = (const float*)d_in[0];
    const float* dist   = (const float*)d_in[1];
    const int*   nbr    = (const int*)  d_in[2];
    const float* WI_pre = (const float*)d_in[3];
    const float* WA_pre = (const float*)d_in[4];
    const float* WS_pre = (const float*)d_in[5];
    const float* WI_post= (const float*)d_in[6];
    const float* WA_post= (const float*)d_in[7];
    const float* WS_post= (const float*)d_in[8];
    const float* Wd     = (const float*)d_in[9];
    const float* bd     = (const float*)d_in[10];
    float* out = (float*)d_out;

    k_transW<<<(6 * EMB * EMB + 255) / 256, 256>>>(WI_pre, WA_pre, WS_pre,
                                                   WI_post, WA_post, WS_post);
    k_decompose<<<(NC + 255) / 256, 256>>>(X);
    k_edge<<<(NEDGE + 127) / 128, 128>>>(dist, nbr);
    dim3 gt((NNODE + 127) / 128, 9);
    k_tlin<<<gt, 256>>>(0);
    k_coeff<<<(NNODE + NODES_PER_BLK - 1) / NODES_PER_BLK, 192>>>(Wd, bd);
    k_mix2<<<(NC + 255) / 256, 256>>>();
    k_tlin<<<gt, 256>>>(3);
    k_final<<<(NC + 255) / 256, 256>>>(out);
}